// round 11
// baseline (speedup 1.0000x reference)
#include <cuda_runtime.h>
#include <cuda_fp16.h>
#include <cstdint>

#define T_STEPS 512
#define BATCH   64
#define HDIM    1024
#define G4      4096
#define KDIM    1024
#define NCTA    128
#define SLOTS   8192            // uint2 fragment slots per CTA per array
#define ASTR    36              // A smem row stride (32 pairs + 4 pad)
#define RING    8               // Zx ring slots per CTA (lookahead = 4)

__device__ uint2 g_WfragH[(size_t)NCTA * SLOTS];   // w_hh frags
__device__ uint2 g_WfragM[(size_t)NCTA * SLOTS];
__device__ uint2 g_XfragH[(size_t)NCTA * SLOTS];   // w_ih frags
__device__ uint2 g_XfragM[(size_t)NCTA * SLOTS];
__device__ float g_Zring[(size_t)NCTA * RING * BATCH * 32];
__device__ unsigned g_flags[NCTA * 32];            // barrier flags, 128B apart

// ---------------------------------------------------------------- helpers
__device__ __forceinline__ void split_pair(float e, float o, uint32_t& ph, uint32_t& pm) {
    __half2 hp = __floats2half2_rn(e, o);
    float2 hf = __half22float2(hp);
    __half2 mp = __floats2half2_rn(e - hf.x, o - hf.y);
    ph = *reinterpret_cast<uint32_t*>(&hp);
    pm = *reinterpret_cast<uint32_t*>(&mp);
}
__device__ __forceinline__ void mma16(float* c, const uint32_t* a, const uint32_t* b) {
    asm volatile(
        "mma.sync.aligned.m16n8k16.row.col.f32.f16.f16.f32 "
        "{%0,%1,%2,%3},{%4,%5,%6,%7},{%8,%9},{%0,%1,%2,%3};\n"
        : "+f"(c[0]), "+f"(c[1]), "+f"(c[2]), "+f"(c[3])
        : "r"(a[0]), "r"(a[1]), "r"(a[2]), "r"(a[3]), "r"(b[0]), "r"(b[1]));
}
__device__ __forceinline__ void mma16h(uint32_t* c, const uint32_t* a, const uint32_t* b) {
    asm volatile(
        "mma.sync.aligned.m16n8k16.row.col.f16.f16.f16.f16 "
        "{%0,%1},{%2,%3,%4,%5},{%6,%7},{%0,%1};\n"
        : "+r"(c[0]), "+r"(c[1])
        : "r"(a[0]), "r"(a[1]), "r"(a[2]), "r"(a[3]), "r"(b[0]), "r"(b[1]));
}
__device__ __forceinline__ void merge_cross(float* acc, const uint32_t* cx) {
    float2 lo = __half22float2(*reinterpret_cast<const __half2*>(&cx[0]));
    float2 hi = __half22float2(*reinterpret_cast<const __half2*>(&cx[1]));
    acc[0] += lo.x; acc[1] += lo.y; acc[2] += hi.x; acc[3] += hi.y;
}
__device__ __forceinline__ float sigmf(float x) { return 1.0f / (1.0f + expf(-x)); }

// ====== wfrag: permute w_hh AND w_ih into per-CTA fragment order ==========
__global__ void __launch_bounds__(256)
wfrag_kernel(const float* __restrict__ w_hh, const float* __restrict__ w_ih) {
    size_t s = (size_t)blockIdx.x * 256 + threadIdx.x;
    if (s < NCTA) g_flags[s * 32] = 0u;
    int cta = (int)(s >> 13);
    int r = (int)(s & (SLOTS - 1));
    int lane = r & 31, q = r >> 5;
    int nt = q & 1, wn = (q >> 1) & 1, kk = (q >> 2) & 3, c = q >> 4;
    int g = lane >> 2, tg = lane & 3;
    int row = wn * 16 + nt * 8 + g;
    size_t R = (size_t)((row >> 3) * HDIM + cta * 8 + (row & 7));
    int p0 = c * 32 + kk * 8 + tg;
    {
        const float* wr = w_hh + R * KDIM;
        uint32_t h0w, m0w, h1w, m1w;
        split_pair(wr[2 * p0],     wr[2 * p0 + 1], h0w, m0w);
        split_pair(wr[2 * p0 + 8], wr[2 * p0 + 9], h1w, m1w);
        g_WfragH[s] = make_uint2(h0w, h1w);
        g_WfragM[s] = make_uint2(m0w, m1w);
    }
    {
        const float* wr = w_ih + R * KDIM;
        uint32_t h0w, m0w, h1w, m1w;
        split_pair(wr[2 * p0],     wr[2 * p0 + 1], h0w, m0w);
        split_pair(wr[2 * p0 + 8], wr[2 * p0 + 9], h1w, m1w);
        g_XfragH[s] = make_uint2(h0w, h1w);
        g_XfragM[s] = make_uint2(m0w, m1w);
    }
}

// ============ Fused persistent kernel: recurrence + self-produced Zx =======
extern __shared__ char rsm[];
#define SA4(buf, hm, row, col) sAu[((((buf) * 2 + (hm)) * 64 + (row)) * ASTR) + (col)]
__global__ void __launch_bounds__(256, 1)
recur_kernel(const float* __restrict__ x, const float* __restrict__ h0,
             const float* __restrict__ c0, const float* __restrict__ b_ih,
             const float* __restrict__ b_hh, const int* __restrict__ biasflag,
             float* __restrict__ out) {
    uint2*    sWfH = (uint2*)rsm;
    uint2*    sWfM = sWfH + SLOTS;
    uint32_t* sAu  = (uint32_t*)(sWfM + SLOTS);          // [4 buf][2 hm][64][ASTR]
    float*    zsm  = (float*)(sAu + 4 * 2 * 64 * ASTR);
    __shared__ float sbias[32];

    int tid = threadIdx.x, warp = tid >> 5, lane = tid & 31;
    int g = lane >> 2, tg = lane & 3;
    int wm = warp & 3, wn = warp >> 2;
    int j0 = blockIdx.x * 8;

    // Resident w_hh fragments
    {
        const uint2* gH = g_WfragH + (size_t)blockIdx.x * SLOTS;
        const uint2* gM = g_WfragM + (size_t)blockIdx.x * SLOTS;
        for (int i = tid; i < SLOTS; i += 256) {
            sWfH[i] = gH[i];
            sWfM[i] = gM[i];
        }
    }
    if (tid < 32) {
        int gcol = (tid >> 3) * 1024 + j0 + (tid & 7);
        sbias[tid] = (*biasflag) ? (b_ih[gcol] + b_hh[gcol]) : 0.0f;
    }

    int b0e = tid >> 3, jj0 = tid & 7;
    int b1e = (tid + 256) >> 3, jj1 = (tid + 256) & 7;
    float creg0 = c0[b0e * HDIM + j0 + jj0];
    float creg1 = c0[b1e * HDIM + j0 + jj1];
    float buf0[4] = {0.f, 0.f, 0.f, 0.f};
    float buf1[4] = {0.f, 0.f, 0.f, 0.f};
    float hlast0 = 0.f, hlast1 = 0.f;

    int arow[4], ac4[4];
#pragma unroll
    for (int it = 0; it < 4; it++) {
        int i = tid + it * 256;
        arow[it] = i >> 4;
        ac4[it] = i & 15;
    }

    const uint2* gXH = g_XfragH + (size_t)blockIdx.x * SLOTS;
    const uint2* gXM = g_XfragM + (size_t)blockIdx.x * SLOTS;

    float zx0[4], zx1[4];
    __syncthreads();   // W fragments + sbias visible

    for (int t = -4; t < T_STEPS; t++) {
        // ================= recurrence GEMM + gates (t >= 0) =================
        if (t >= 0) {
            const float* hsrc = (t == 0) ? h0 : (out + (size_t)(t - 1) * BATCH * HDIM);

            float4 va[2][4];
#pragma unroll
            for (int half = 0; half < 2; half++)
#pragma unroll
                for (int it = 0; it < 4; it++)
                    va[half][it] = *(const float4*)(hsrc + (size_t)arow[it] * HDIM +
                                                    half * 64 + ac4[it] * 4);

            float acc[2][4] = {};
            uint32_t accx[2][2] = {};
#pragma unroll 1
            for (int cc = 0; cc < 8; cc++) {
#pragma unroll
                for (int half = 0; half < 2; half++) {
                    int bsel = (2 * cc + half) & 3;
#pragma unroll
                    for (int it = 0; it < 4; it++) {
                        split_pair(va[half][it].x, va[half][it].y,
                                   SA4(bsel, 0, arow[it], ac4[it] * 2),
                                   SA4(bsel, 1, arow[it], ac4[it] * 2));
                        split_pair(va[half][it].z, va[half][it].w,
                                   SA4(bsel, 0, arow[it], ac4[it] * 2 + 1),
                                   SA4(bsel, 1, arow[it], ac4[it] * 2 + 1));
                    }
                }
                __syncthreads();
                if (cc < 7) {
#pragma unroll
                    for (int half = 0; half < 2; half++) {
                        int k0 = (2 * cc + 2 + half) * 64;
#pragma unroll
                        for (int it = 0; it < 4; it++)
                            va[half][it] = *(const float4*)(hsrc + (size_t)arow[it] * HDIM +
                                                            k0 + ac4[it] * 4);
                    }
                }
#pragma unroll
                for (int half = 0; half < 2; half++) {
                    int c = 2 * cc + half, bsel = c & 3;
#pragma unroll
                    for (int kk = 0; kk < 4; kk++) {
                        uint32_t afh[4], afm[4];
                        int r = wm * 16;
                        afh[0] = SA4(bsel, 0, r + g, kk * 8 + tg);
                        afh[1] = SA4(bsel, 0, r + g + 8, kk * 8 + tg);
                        afh[2] = SA4(bsel, 0, r + g, kk * 8 + tg + 4);
                        afh[3] = SA4(bsel, 0, r + g + 8, kk * 8 + tg + 4);
                        afm[0] = SA4(bsel, 1, r + g, kk * 8 + tg);
                        afm[1] = SA4(bsel, 1, r + g + 8, kk * 8 + tg);
                        afm[2] = SA4(bsel, 1, r + g, kk * 8 + tg + 4);
                        afm[3] = SA4(bsel, 1, r + g + 8, kk * 8 + tg + 4);
#pragma unroll
                        for (int nt = 0; nt < 2; nt++) {
                            int fb = (((c * 4 + kk) * 2 + wn) * 2 + nt) * 32 + lane;
                            uint2 bh = sWfH[fb], bm = sWfM[fb];
                            uint32_t bfh[2] = {bh.x, bh.y};
                            uint32_t bfm[2] = {bm.x, bm.y};
                            mma16h(accx[nt], afh, bfm);
                            mma16h(accx[nt], afm, bfh);
                            mma16(acc[nt], afh, bfh);
                        }
                    }
                }
            }
            merge_cross(acc[0], accx[0]);
            merge_cross(acc[1], accx[1]);

            {
                int r0 = wm * 16 + g;
#pragma unroll
                for (int nt = 0; nt < 2; nt++) {
                    int cc2 = wn * 16 + nt * 8 + 2 * tg;
                    zsm[r0 * 33 + cc2]           = acc[nt][0];
                    zsm[r0 * 33 + cc2 + 1]       = acc[nt][1];
                    zsm[(r0 + 8) * 33 + cc2]     = acc[nt][2];
                    zsm[(r0 + 8) * 33 + cc2 + 1] = acc[nt][3];
                }
            }
            __syncthreads();

            {
                float zi = zsm[b0e * 33 + jj0]      + zx0[0];
                float zf = zsm[b0e * 33 + 8 + jj0]  + zx0[1];
                float zg = zsm[b0e * 33 + 16 + jj0] + zx0[2];
                float zo = zsm[b0e * 33 + 24 + jj0] + zx0[3];
                float cn = sigmf(zf) * creg0 + sigmf(zi) * tanhf(zg);
                float h = sigmf(zo) * tanhf(cn);
                int idx = t & 3;
                if (t >= 4) h += buf0[idx];
                buf0[idx] = h;
                creg0 = cn;
                hlast0 = h;
                out[(size_t)t * BATCH * HDIM + b0e * HDIM + j0 + jj0] = h;
            }
            {
                float zi = zsm[b1e * 33 + jj1]      + zx1[0];
                float zf = zsm[b1e * 33 + 8 + jj1]  + zx1[1];
                float zg = zsm[b1e * 33 + 16 + jj1] + zx1[2];
                float zo = zsm[b1e * 33 + 24 + jj1] + zx1[3];
                float cn = sigmf(zf) * creg1 + sigmf(zi) * tanhf(zg);
                float h = sigmf(zo) * tanhf(cn);
                int idx = t & 3;
                if (t >= 4) h += buf1[idx];
                buf1[idx] = h;
                creg1 = cn;
                hlast1 = h;
                out[(size_t)t * BATCH * HDIM + b1e * HDIM + j0 + jj1] = h;
            }

            // Release: my h(t) writes are ordered behind this flag
            __syncthreads();
            if (tid == 0)
                asm volatile("st.release.gpu.u32 [%0], %1;"
                             :: "l"(&g_flags[blockIdx.x * 32]), "r"((unsigned)(t + 1)) : "memory");
        }

        // ============ xproj stage for step tp = t + 4 (fills barrier) ======
        if (t + 4 < T_STEPS) {
            int tp = t + 4;
            const float* xsrc = x + (size_t)tp * BATCH * KDIM;

            float4 va[2][4];
#pragma unroll
            for (int half = 0; half < 2; half++)
#pragma unroll
                for (int it = 0; it < 4; it++)
                    va[half][it] = *(const float4*)(xsrc + (size_t)arow[it] * KDIM +
                                                    half * 64 + ac4[it] * 4);
            // W_ih frag double-buffer (chunk granularity)
            uint2 wbH[2][8], wbM[2][8];
#pragma unroll
            for (int kk = 0; kk < 4; kk++)
#pragma unroll
                for (int nt = 0; nt < 2; nt++) {
                    int fb = (((0 * 4 + kk) * 2 + wn) * 2 + nt) * 32 + lane;
                    wbH[0][kk * 2 + nt] = gXH[fb];
                    wbM[0][kk * 2 + nt] = gXM[fb];
                }

            float acc[2][4] = {};
            uint32_t accx[2][2] = {};
#pragma unroll 1
            for (int cc = 0; cc < 8; cc++) {
#pragma unroll
                for (int half = 0; half < 2; half++) {
                    int bsel = (2 * cc + half) & 3;
#pragma unroll
                    for (int it = 0; it < 4; it++) {
                        split_pair(va[half][it].x, va[half][it].y,
                                   SA4(bsel, 0, arow[it], ac4[it] * 2),
                                   SA4(bsel, 1, arow[it], ac4[it] * 2));
                        split_pair(va[half][it].z, va[half][it].w,
                                   SA4(bsel, 0, arow[it], ac4[it] * 2 + 1),
                                   SA4(bsel, 1, arow[it], ac4[it] * 2 + 1));
                    }
                }
                __syncthreads();
                if (cc < 7) {
#pragma unroll
                    for (int half = 0; half < 2; half++) {
                        int k0 = (2 * cc + 2 + half) * 64;
#pragma unroll
                        for (int it = 0; it < 4; it++)
                            va[half][it] = *(const float4*)(xsrc + (size_t)arow[it] * KDIM +
                                                            k0 + ac4[it] * 4);
                    }
                }
#pragma unroll
                for (int half = 0; half < 2; half++) {
                    int c = 2 * cc + half, bsel = c & 3;
                    if (c < 15) {   // prefetch W_ih frags for chunk c+1
#pragma unroll
                        for (int kk = 0; kk < 4; kk++)
#pragma unroll
                            for (int nt = 0; nt < 2; nt++) {
                                int fb = ((((c + 1) * 4 + kk) * 2 + wn) * 2 + nt) * 32 + lane;
                                wbH[half ^ 1][kk * 2 + nt] = gXH[fb];
                                wbM[half ^ 1][kk * 2 + nt] = gXM[fb];
                            }
                    }
#pragma unroll
                    for (int kk = 0; kk < 4; kk++) {
                        uint32_t afh[4], afm[4];
                        int r = wm * 16;
                        afh[0] = SA4(bsel, 0, r + g, kk * 8 + tg);
                        afh[1] = SA4(bsel, 0, r + g + 8, kk * 8 + tg);
                        afh[2] = SA4(bsel, 0, r + g, kk * 8 + tg + 4);
                        afh[3] = SA4(bsel, 0, r + g + 8, kk * 8 + tg + 4);
                        afm[0] = SA4(bsel, 1, r + g, kk * 8 + tg);
                        afm[1] = SA4(bsel, 1, r + g + 8, kk * 8 + tg);
                        afm[2] = SA4(bsel, 1, r + g, kk * 8 + tg + 4);
                        afm[3] = SA4(bsel, 1, r + g + 8, kk * 8 + tg + 4);
#pragma unroll
                        for (int nt = 0; nt < 2; nt++) {
                            uint2 bh = wbH[half][kk * 2 + nt];
                            uint2 bm = wbM[half][kk * 2 + nt];
                            uint32_t bfh[2] = {bh.x, bh.y};
                            uint32_t bfm[2] = {bm.x, bm.y};
                            mma16h(accx[nt], afh, bfm);
                            mma16h(accx[nt], afm, bfh);
                            mma16(acc[nt], afh, bfh);
                        }
                    }
                }
            }
            merge_cross(acc[0], accx[0]);
            merge_cross(acc[1], accx[1]);

            // Epilogue: write Zx tile (+bias) into own ring slot (L2, .cg)
            float* ring = g_Zring + ((size_t)blockIdx.x * RING + (tp & (RING - 1))) * (BATCH * 32);
            {
                int r0 = wm * 16 + g;
#pragma unroll
                for (int nt = 0; nt < 2; nt++) {
                    int cw = wn * 16 + nt * 8 + 2 * tg;
                    __stcg(ring + r0 * 32 + cw,           acc[nt][0] + sbias[cw]);
                    __stcg(ring + r0 * 32 + cw + 1,       acc[nt][1] + sbias[cw + 1]);
                    __stcg(ring + (r0 + 8) * 32 + cw,     acc[nt][2] + sbias[cw]);
                    __stcg(ring + (r0 + 8) * 32 + cw + 1, acc[nt][3] + sbias[cw + 1]);
                }
            }
            __threadfence();   // push ring stores toward L2 visibility
        }

        // Prefetch next step's Zx from ring (written >= 3 iterations ago)
        if (t + 1 >= 0 && t + 1 < T_STEPS) {
            const float* ring = g_Zring +
                ((size_t)blockIdx.x * RING + ((t + 1) & (RING - 1))) * (BATCH * 32);
#pragma unroll
            for (int q = 0; q < 4; q++) {
                zx0[q] = __ldcg(ring + b0e * 32 + q * 8 + jj0);
                zx1[q] = __ldcg(ring + b1e * 32 + q * 8 + jj1);
            }
        }

        // Barrier poll (flags long since posted — xproj work absorbed skew)
        if (t >= 0 && t + 1 < T_STEPS) {
            if (tid < NCTA) {
                unsigned v;
                do {
                    asm volatile("ld.acquire.gpu.u32 %0, [%1];"
                                 : "=r"(v) : "l"(&g_flags[tid * 32]) : "memory");
                } while (v < (unsigned)(t + 1));
            }
        }
        __syncthreads();
    }

    float* hfin = out + (size_t)T_STEPS * BATCH * HDIM;
    float* cfin = hfin + BATCH * HDIM;
    hfin[b0e * HDIM + j0 + jj0] = hlast0;
    hfin[b1e * HDIM + j0 + jj1] = hlast1;
    cfin[b0e * HDIM + j0 + jj0] = creg0;
    cfin[b1e * HDIM + j0 + jj1] = creg1;
}

extern "C" void kernel_launch(void* const* d_in, const int* in_sizes, int n_in,
                              void* d_out, int out_size) {
    const float* x    = (const float*)d_in[0];
    const float* h0   = (const float*)d_in[1];
    const float* c0   = (const float*)d_in[2];
    const float* w_ih = (const float*)d_in[3];
    const float* w_hh = (const float*)d_in[4];
    const float* b_ih = (const float*)d_in[5];
    const float* b_hh = (const float*)d_in[6];
    const int* bias   = (const int*)d_in[7];
    float* out = (float*)d_out;

    const int RSMEM = SLOTS * 8 * 2 + 4 * 2 * 64 * ASTR * 4 + 64 * 33 * 4; // 213248
    cudaFuncSetAttribute(recur_kernel, cudaFuncAttributeMaxDynamicSharedMemorySize, RSMEM);

    wfrag_kernel<<<(NCTA * SLOTS) / 256, 256>>>(w_hh, w_ih);
    recur_kernel<<<NCTA, 256, RSMEM>>>(x, h0, c0, b_ih, b_hh, bias, out);
}

// round 12
// speedup vs baseline: 1.3008x; 1.3008x over previous
#include <cuda_runtime.h>
#include <cuda_fp16.h>
#include <cstdint>

#define T_STEPS 512
#define BATCH   64
#define IDIM    1024
#define HDIM    1024
#define G4      4096
#define KDIM    1024
#define NCTA    128
#define SLOTS   8192            // uint2 fragment slots per CTA per array
#define ASTR    36              // recur A smem row stride (32 pairs + 4 pad)
#define XSTR    20              // xproj smem row stride (16 pairs + 4 pad)

__device__ float g_Zx[(size_t)T_STEPS * BATCH * G4];
__device__ uint2 g_WfragH[(size_t)NCTA * SLOTS];
__device__ uint2 g_WfragM[(size_t)NCTA * SLOTS];
__device__ unsigned g_flags[NCTA * 32];   // distributed barrier flags, 128B apart

// ---------------------------------------------------------------- helpers
__device__ __forceinline__ void split_pair(float e, float o, uint32_t& ph, uint32_t& pm) {
    __half2 hp = __floats2half2_rn(e, o);
    float2 hf = __half22float2(hp);
    __half2 mp = __floats2half2_rn(e - hf.x, o - hf.y);
    ph = *reinterpret_cast<uint32_t*>(&hp);
    pm = *reinterpret_cast<uint32_t*>(&mp);
}
__device__ __forceinline__ void mma16(float* c, const uint32_t* a, const uint32_t* b) {
    asm volatile(
        "mma.sync.aligned.m16n8k16.row.col.f32.f16.f16.f32 "
        "{%0,%1,%2,%3},{%4,%5,%6,%7},{%8,%9},{%0,%1,%2,%3};\n"
        : "+f"(c[0]), "+f"(c[1]), "+f"(c[2]), "+f"(c[3])
        : "r"(a[0]), "r"(a[1]), "r"(a[2]), "r"(a[3]), "r"(b[0]), "r"(b[1]));
}
__device__ __forceinline__ void mma16h(uint32_t* c, const uint32_t* a, const uint32_t* b) {
    asm volatile(
        "mma.sync.aligned.m16n8k16.row.col.f16.f16.f16.f16 "
        "{%0,%1},{%2,%3,%4,%5},{%6,%7},{%0,%1};\n"
        : "+r"(c[0]), "+r"(c[1])
        : "r"(a[0]), "r"(a[1]), "r"(a[2]), "r"(a[3]), "r"(b[0]), "r"(b[1]));
}
__device__ __forceinline__ void merge_cross(float* acc, const uint32_t* cx) {
    float2 lo = __half22float2(*reinterpret_cast<const __half2*>(&cx[0]));
    float2 hi = __half22float2(*reinterpret_cast<const __half2*>(&cx[1]));
    acc[0] += lo.x; acc[1] += lo.y; acc[2] += hi.x; acc[3] += hi.y;
}
__device__ __forceinline__ float sigmf(float x) { return 1.0f / (1.0f + expf(-x)); }

// ====== wfrag: permute w_hh into per-CTA MMA-fragment order; reset flags ===
__global__ void __launch_bounds__(256)
wfrag_kernel(const float* __restrict__ w_hh) {
    size_t s = (size_t)blockIdx.x * 256 + threadIdx.x;
    if (s < NCTA) g_flags[s * 32] = 0u;
    int cta = (int)(s >> 13);
    int r = (int)(s & (SLOTS - 1));
    int lane = r & 31, q = r >> 5;
    int nt = q & 1, wn = (q >> 1) & 1, kk = (q >> 2) & 3, c = q >> 4;
    int g = lane >> 2, tg = lane & 3;
    int row = wn * 16 + nt * 8 + g;
    size_t R = (size_t)((row >> 3) * HDIM + cta * 8 + (row & 7));
    int p0 = c * 32 + kk * 8 + tg;
    const float* wr = w_hh + R * KDIM;
    uint32_t h0w, m0w, h1w, m1w;
    split_pair(wr[2 * p0],     wr[2 * p0 + 1], h0w, m0w);
    split_pair(wr[2 * p0 + 8], wr[2 * p0 + 9], h1w, m1w);
    g_WfragH[s] = make_uint2(h0w, h1w);
    g_WfragM[s] = make_uint2(m0w, m1w);
}

// ============ Phase 1: Z_x = x @ w_ih^T + bias (R8/R10-exact) ==============
extern __shared__ uint32_t xsm_u[];
#define XA(arr, buf, row, col) xsm_u[((((arr) * 2 + (buf)) * 128 + (row)) * XSTR) + (col)]
__global__ void __launch_bounds__(256)
xproj_kernel(const float* __restrict__ x, const float* __restrict__ w_ih,
             const float* __restrict__ b_ih, const float* __restrict__ b_hh,
             const int* __restrict__ biasflag) {
    int tid = threadIdx.x, warp = tid >> 5, lane = tid & 31;
    int g = lane >> 2, tg = lane & 3;
    int wm = warp >> 2, wn = warp & 3;
    int m_base = blockIdx.y * 128, n_base = blockIdx.x * 128;

    int srow[4], sc4[4];
#pragma unroll
    for (int it = 0; it < 4; it++) {
        int i = tid + it * 256;
        srow[it] = i >> 3;
        sc4[it] = i & 7;
    }

    float acc[4][4][4] = {};
    uint32_t accx[4][4][2] = {};
    float4 av[4], bv[4];

#pragma unroll
    for (int it = 0; it < 4; it++) {
        av[it] = *(const float4*)(x    + (size_t)(m_base + srow[it]) * KDIM + sc4[it] * 4);
        bv[it] = *(const float4*)(w_ih + (size_t)(n_base + srow[it]) * KDIM + sc4[it] * 4);
    }
#pragma unroll
    for (int it = 0; it < 4; it++) {
        split_pair(av[it].x, av[it].y, XA(0, 0, srow[it], sc4[it] * 2), XA(1, 0, srow[it], sc4[it] * 2));
        split_pair(av[it].z, av[it].w, XA(0, 0, srow[it], sc4[it] * 2 + 1), XA(1, 0, srow[it], sc4[it] * 2 + 1));
        split_pair(bv[it].x, bv[it].y, XA(2, 0, srow[it], sc4[it] * 2), XA(3, 0, srow[it], sc4[it] * 2));
        split_pair(bv[it].z, bv[it].w, XA(2, 0, srow[it], sc4[it] * 2 + 1), XA(3, 0, srow[it], sc4[it] * 2 + 1));
    }

#pragma unroll 1
    for (int c = 0; c < 32; c++) {
        if (c < 31) {
            int k0 = (c + 1) * 32;
#pragma unroll
            for (int it = 0; it < 4; it++) {
                av[it] = *(const float4*)(x    + (size_t)(m_base + srow[it]) * KDIM + k0 + sc4[it] * 4);
                bv[it] = *(const float4*)(w_ih + (size_t)(n_base + srow[it]) * KDIM + k0 + sc4[it] * 4);
            }
        }
        __syncthreads();
        if (c < 31) {
            int nb = (c + 1) & 1;
#pragma unroll
            for (int it = 0; it < 4; it++) {
                split_pair(av[it].x, av[it].y, XA(0, nb, srow[it], sc4[it] * 2), XA(1, nb, srow[it], sc4[it] * 2));
                split_pair(av[it].z, av[it].w, XA(0, nb, srow[it], sc4[it] * 2 + 1), XA(1, nb, srow[it], sc4[it] * 2 + 1));
                split_pair(bv[it].x, bv[it].y, XA(2, nb, srow[it], sc4[it] * 2), XA(3, nb, srow[it], sc4[it] * 2));
                split_pair(bv[it].z, bv[it].w, XA(2, nb, srow[it], sc4[it] * 2 + 1), XA(3, nb, srow[it], sc4[it] * 2 + 1));
            }
        }
        int bsel = c & 1;
#pragma unroll
        for (int kk = 0; kk < 2; kk++) {
            uint32_t afh[4][4], afm[4][4];
#pragma unroll
            for (int mi = 0; mi < 4; mi++) {
                int r = wm * 64 + mi * 16;
                afh[mi][0] = XA(0, bsel, r + g, kk * 8 + tg);
                afh[mi][1] = XA(0, bsel, r + g + 8, kk * 8 + tg);
                afh[mi][2] = XA(0, bsel, r + g, kk * 8 + tg + 4);
                afh[mi][3] = XA(0, bsel, r + g + 8, kk * 8 + tg + 4);
                afm[mi][0] = XA(1, bsel, r + g, kk * 8 + tg);
                afm[mi][1] = XA(1, bsel, r + g + 8, kk * 8 + tg);
                afm[mi][2] = XA(1, bsel, r + g, kk * 8 + tg + 4);
                afm[mi][3] = XA(1, bsel, r + g + 8, kk * 8 + tg + 4);
            }
#pragma unroll
            for (int ni = 0; ni < 4; ni++) {
                int rn = wn * 32 + ni * 8 + g;
                uint32_t bfh[2] = {XA(2, bsel, rn, kk * 8 + tg), XA(2, bsel, rn, kk * 8 + tg + 4)};
                uint32_t bfm[2] = {XA(3, bsel, rn, kk * 8 + tg), XA(3, bsel, rn, kk * 8 + tg + 4)};
#pragma unroll
                for (int mi = 0; mi < 4; mi++) {
                    mma16h(accx[mi][ni], afh[mi], bfm);
                    mma16h(accx[mi][ni], afm[mi], bfh);
                    mma16(acc[mi][ni], afh[mi], bfh);
                }
            }
        }
    }

    int bflag = *biasflag;
#pragma unroll
    for (int mi = 0; mi < 4; mi++) {
#pragma unroll
        for (int ni = 0; ni < 4; ni++) {
            merge_cross(acc[mi][ni], accx[mi][ni]);
            int row0 = m_base + wm * 64 + mi * 16 + g;
            int col0 = n_base + wn * 32 + ni * 8 + 2 * tg;
            float bs0 = bflag ? (b_ih[col0] + b_hh[col0]) : 0.0f;
            float bs1 = bflag ? (b_ih[col0 + 1] + b_hh[col0 + 1]) : 0.0f;
            g_Zx[(size_t)row0 * G4 + col0]           = acc[mi][ni][0] + bs0;
            g_Zx[(size_t)row0 * G4 + col0 + 1]       = acc[mi][ni][1] + bs1;
            g_Zx[(size_t)(row0 + 8) * G4 + col0]     = acc[mi][ni][2] + bs0;
            g_Zx[(size_t)(row0 + 8) * G4 + col0 + 1] = acc[mi][ni][3] + bs1;
        }
    }
}

// ============ Phase 2: recurrence — 512 threads (16 warps), R10 order ======
extern __shared__ char rsm[];
#define SA4(buf, hm, row, col) sAu[((((buf) * 2 + (hm)) * 64 + (row)) * ASTR) + (col)]
__global__ void __launch_bounds__(512, 1)
recur_kernel(const float* __restrict__ h0, const float* __restrict__ c0,
             float* __restrict__ out) {
    uint2*    sWfH = (uint2*)rsm;
    uint2*    sWfM = sWfH + SLOTS;
    uint32_t* sAu  = (uint32_t*)(sWfM + SLOTS);          // [4 buf][2 hm][64][ASTR]
    float*    zsm  = (float*)(sAu + 4 * 2 * 64 * ASTR);

    int tid = threadIdx.x, warp = tid >> 5, lane = tid & 31;
    int g = lane >> 2, tg = lane & 3;
    int wm = warp & 3, wn = warp >> 2;   // wn 0..3: one n8 block per warp
    int j0 = blockIdx.x * 8;

    {
        const uint2* gH = g_WfragH + (size_t)blockIdx.x * SLOTS;
        const uint2* gM = g_WfragM + (size_t)blockIdx.x * SLOTS;
        for (int i = tid; i < SLOTS; i += 512) {
            sWfH[i] = gH[i];
            sWfM[i] = gM[i];
        }
    }

    // Epilogue ownership: exactly one (b, jj) per thread
    int b = tid >> 3, jj = tid & 7;
    float creg = c0[b * HDIM + j0 + jj];
    float sbuf[4] = {0.f, 0.f, 0.f, 0.f};
    float hlast = 0.f;

    // A-tile loader slots: 1024 float4 per 64x64 chunk, 2 per thread
    int arow[2], ac4[2];
#pragma unroll
    for (int it = 0; it < 2; it++) {
        int i = tid + it * 512;
        arow[it] = i >> 4;
        ac4[it] = i & 15;
    }

    size_t zb = (size_t)b * G4 + (j0 + jj);
    float zx[4];
#pragma unroll
    for (int q = 0; q < 4; q++)
        zx[q] = g_Zx[zb + (size_t)q * 1024];
    __syncthreads();   // W fragments visible

    for (int t = 0; t < T_STEPS; t++) {
        const float* hsrc = (t == 0) ? h0 : (out + (size_t)(t - 1) * BATCH * HDIM);

        // Prologue: LDG chunks 0,1
        float4 va[2][2];
#pragma unroll
        for (int half = 0; half < 2; half++)
#pragma unroll
            for (int it = 0; it < 2; it++)
                va[half][it] = *(const float4*)(hsrc + (size_t)arow[it] * HDIM +
                                                half * 64 + ac4[it] * 4);

        float acc[4] = {};
        uint32_t accx[2] = {};
#pragma unroll 1
        for (int cc = 0; cc < 8; cc++) {
            // split chunks 2cc, 2cc+1 (R10 order: split -> sync -> LDG -> MMA)
#pragma unroll
            for (int half = 0; half < 2; half++) {
                int bsel = (2 * cc + half) & 3;
#pragma unroll
                for (int it = 0; it < 2; it++) {
                    split_pair(va[half][it].x, va[half][it].y,
                               SA4(bsel, 0, arow[it], ac4[it] * 2),
                               SA4(bsel, 1, arow[it], ac4[it] * 2));
                    split_pair(va[half][it].z, va[half][it].w,
                               SA4(bsel, 0, arow[it], ac4[it] * 2 + 1),
                               SA4(bsel, 1, arow[it], ac4[it] * 2 + 1));
                }
            }
            __syncthreads();
            if (cc < 7) {
#pragma unroll
                for (int half = 0; half < 2; half++) {
                    int k0 = (2 * cc + 2 + half) * 64;
#pragma unroll
                    for (int it = 0; it < 2; it++)
                        va[half][it] = *(const float4*)(hsrc + (size_t)arow[it] * HDIM +
                                                        k0 + ac4[it] * 4);
                }
            }
#pragma unroll
            for (int half = 0; half < 2; half++) {
                int c = 2 * cc + half, bsel = c & 3;
#pragma unroll
                for (int kk = 0; kk < 4; kk++) {
                    uint32_t afh[4], afm[4];
                    int r = wm * 16;
                    afh[0] = SA4(bsel, 0, r + g, kk * 8 + tg);
                    afh[1] = SA4(bsel, 0, r + g + 8, kk * 8 + tg);
                    afh[2] = SA4(bsel, 0, r + g, kk * 8 + tg + 4);
                    afh[3] = SA4(bsel, 0, r + g + 8, kk * 8 + tg + 4);
                    afm[0] = SA4(bsel, 1, r + g, kk * 8 + tg);
                    afm[1] = SA4(bsel, 1, r + g + 8, kk * 8 + tg);
                    afm[2] = SA4(bsel, 1, r + g, kk * 8 + tg + 4);
                    afm[3] = SA4(bsel, 1, r + g + 8, kk * 8 + tg + 4);
                    int fb = ((c * 4 + kk) * 4 + wn) * 32 + lane;
                    uint2 bh = sWfH[fb], bm = sWfM[fb];
                    uint32_t bfh[2] = {bh.x, bh.y};
                    uint32_t bfm[2] = {bm.x, bm.y};
                    mma16h(accx, afh, bfm);
                    mma16h(accx, afm, bfh);
                    mma16(acc, afh, bfh);
                }
            }
        }
        merge_cross(acc, accx);

        // Scatter z tile: each warp 16 rows x 8 cols
        {
            int r0 = wm * 16 + g;
            int cw = wn * 8 + 2 * tg;
            zsm[r0 * 33 + cw]           = acc[0];
            zsm[r0 * 33 + cw + 1]       = acc[1];
            zsm[(r0 + 8) * 33 + cw]     = acc[2];
            zsm[(r0 + 8) * 33 + cw + 1] = acc[3];
        }
        __syncthreads();

        // Gate math + skip queue (one element per thread)
        {
            float zi = zsm[b * 33 + jj]      + zx[0];
            float zf = zsm[b * 33 + 8 + jj]  + zx[1];
            float zg = zsm[b * 33 + 16 + jj] + zx[2];
            float zo = zsm[b * 33 + 24 + jj] + zx[3];
            float cn = sigmf(zf) * creg + sigmf(zi) * tanhf(zg);
            float h = sigmf(zo) * tanhf(cn);
            int idx = t & 3;
            if (t >= 4) h += sbuf[idx];
            sbuf[idx] = h;
            creg = cn;
            hlast = h;
            out[(size_t)t * BATCH * HDIM + b * HDIM + j0 + jj] = h;
        }

        // Prefetch next step's Zx before barrier (step-independent)
        if (t + 1 < T_STEPS) {
            size_t zn = (size_t)(t + 1) * BATCH * G4 + zb;
#pragma unroll
            for (int q = 0; q < 4; q++)
                zx[q] = g_Zx[zn + (size_t)q * 1024];
        }

        // Distributed grid barrier: per-CTA release flag + 128-thread poll
        __syncthreads();
        if (tid == 0)
            asm volatile("st.release.gpu.u32 [%0], %1;"
                         :: "l"(&g_flags[blockIdx.x * 32]), "r"((unsigned)(t + 1)) : "memory");
        if (tid < NCTA) {
            unsigned v;
            do {
                asm volatile("ld.acquire.gpu.u32 %0, [%1];"
                             : "=r"(v) : "l"(&g_flags[tid * 32]) : "memory");
            } while (v < (unsigned)(t + 1));
        }
        __syncthreads();
    }

    float* hfin = out + (size_t)T_STEPS * BATCH * HDIM;
    float* cfin = hfin + BATCH * HDIM;
    hfin[b * HDIM + j0 + jj] = hlast;
    cfin[b * HDIM + j0 + jj] = creg;
}

extern "C" void kernel_launch(void* const* d_in, const int* in_sizes, int n_in,
                              void* d_out, int out_size) {
    const float* x    = (const float*)d_in[0];
    const float* h0   = (const float*)d_in[1];
    const float* c0   = (const float*)d_in[2];
    const float* w_ih = (const float*)d_in[3];
    const float* w_hh = (const float*)d_in[4];
    const float* b_ih = (const float*)d_in[5];
    const float* b_hh = (const float*)d_in[6];
    const int* bias   = (const int*)d_in[7];
    float* out = (float*)d_out;

    const int XSMEM = 4 * 2 * 128 * XSTR * 4;                              // 81920
    const int RSMEM = SLOTS * 8 * 2 + 4 * 2 * 64 * ASTR * 4 + 64 * 33 * 4; // 213248
    cudaFuncSetAttribute(xproj_kernel, cudaFuncAttributeMaxDynamicSharedMemorySize, XSMEM);
    cudaFuncSetAttribute(recur_kernel, cudaFuncAttributeMaxDynamicSharedMemorySize, RSMEM);

    wfrag_kernel<<<(NCTA * SLOTS) / 256, 256>>>(w_hh);
    dim3 g1(G4 / 128, (T_STEPS * BATCH) / 128);  // (32, 256)
    xproj_kernel<<<g1, 256, XSMEM>>>(x, w_ih, b_ih, b_hh, bias);
    recur_kernel<<<NCTA, 512, RSMEM>>>(h0, c0, out);
}

// round 13
// speedup vs baseline: 1.4358x; 1.1038x over previous
#include <cuda_runtime.h>
#include <cuda_fp16.h>
#include <cstdint>

#define T_STEPS 512
#define BATCH   64
#define IDIM    1024
#define HDIM    1024
#define G4      4096
#define KDIM    1024
#define KP      (KDIM/2)        // K-pairs per row
#define NCTA    128
#define SLOTS   8192            // uint2 fragment slots per CTA per array
#define ASTR    36              // recur A smem row stride (36 words = 144B, 16B-aligned, conflict-free)
#define XSTR    20              // xproj smem row stride (16 pairs + 4 pad)

__device__ float    g_Zx[(size_t)T_STEPS * BATCH * G4];
__device__ uint2    g_WfragH[(size_t)NCTA * SLOTS];
__device__ uint2    g_WfragM[(size_t)NCTA * SLOTS];
__device__ uint32_t g_HsH[(size_t)(T_STEPS + 1) * BATCH * KP];  // h split hi pairs
__device__ uint32_t g_HsM[(size_t)(T_STEPS + 1) * BATCH * KP];  // h split mid pairs
__device__ unsigned g_flags[NCTA * 32];   // distributed barrier flags, 128B apart

// ---------------------------------------------------------------- helpers
__device__ __forceinline__ void split_pair(float e, float o, uint32_t& ph, uint32_t& pm) {
    __half2 hp = __floats2half2_rn(e, o);
    float2 hf = __half22float2(hp);
    __half2 mp = __floats2half2_rn(e - hf.x, o - hf.y);
    ph = *reinterpret_cast<uint32_t*>(&hp);
    pm = *reinterpret_cast<uint32_t*>(&mp);
}
__device__ __forceinline__ void mma16(float* c, const uint32_t* a, const uint32_t* b) {
    asm volatile(
        "mma.sync.aligned.m16n8k16.row.col.f32.f16.f16.f32 "
        "{%0,%1,%2,%3},{%4,%5,%6,%7},{%8,%9},{%0,%1,%2,%3};\n"
        : "+f"(c[0]), "+f"(c[1]), "+f"(c[2]), "+f"(c[3])
        : "r"(a[0]), "r"(a[1]), "r"(a[2]), "r"(a[3]), "r"(b[0]), "r"(b[1]));
}
__device__ __forceinline__ void mma16h(uint32_t* c, const uint32_t* a, const uint32_t* b) {
    asm volatile(
        "mma.sync.aligned.m16n8k16.row.col.f16.f16.f16.f16 "
        "{%0,%1},{%2,%3,%4,%5},{%6,%7},{%0,%1};\n"
        : "+r"(c[0]), "+r"(c[1])
        : "r"(a[0]), "r"(a[1]), "r"(a[2]), "r"(a[3]), "r"(b[0]), "r"(b[1]));
}
__device__ __forceinline__ void merge_cross(float* acc, const uint32_t* cx) {
    float2 lo = __half22float2(*reinterpret_cast<const __half2*>(&cx[0]));
    float2 hi = __half22float2(*reinterpret_cast<const __half2*>(&cx[1]));
    acc[0] += lo.x; acc[1] += lo.y; acc[2] += hi.x; acc[3] += hi.y;
}
__device__ __forceinline__ float sigmf(float x) { return 1.0f / (1.0f + expf(-x)); }

// ====== wfrag: w_hh -> per-CTA fragment order; h0 -> split pairs; flags=0 ==
__global__ void __launch_bounds__(256)
wfrag_kernel(const float* __restrict__ w_hh, const float* __restrict__ h0) {
    size_t s = (size_t)blockIdx.x * 256 + threadIdx.x;
    if (s < NCTA) g_flags[s * 32] = 0u;
    if (s < (size_t)BATCH * KP) {   // h0 split into slot 0
        int b = (int)(s >> 9), p = (int)(s & 511);
        float2 v = *(const float2*)(h0 + (size_t)b * HDIM + 2 * p);
        uint32_t ph, pm;
        split_pair(v.x, v.y, ph, pm);
        g_HsH[s] = ph;
        g_HsM[s] = pm;
    }
    int cta = (int)(s >> 13);
    int r = (int)(s & (SLOTS - 1));
    int lane = r & 31, q = r >> 5;
    int nt = q & 1, wn = (q >> 1) & 1, kk = (q >> 2) & 3, c = q >> 4;
    int g = lane >> 2, tg = lane & 3;
    int row = wn * 16 + nt * 8 + g;
    size_t R = (size_t)((row >> 3) * HDIM + cta * 8 + (row & 7));
    int p0 = c * 32 + kk * 8 + tg;
    const float* wr = w_hh + R * KDIM;
    uint32_t h0w, m0w, h1w, m1w;
    split_pair(wr[2 * p0],     wr[2 * p0 + 1], h0w, m0w);
    split_pair(wr[2 * p0 + 8], wr[2 * p0 + 9], h1w, m1w);
    g_WfragH[s] = make_uint2(h0w, h1w);
    g_WfragM[s] = make_uint2(m0w, m1w);
}

// ============ Phase 1: Z_x = x @ w_ih^T + bias (R10-exact) =================
extern __shared__ uint32_t xsm_u[];
#define XA(arr, buf, row, col) xsm_u[((((arr) * 2 + (buf)) * 128 + (row)) * XSTR) + (col)]
__global__ void __launch_bounds__(256)
xproj_kernel(const float* __restrict__ x, const float* __restrict__ w_ih,
             const float* __restrict__ b_ih, const float* __restrict__ b_hh,
             const int* __restrict__ biasflag) {
    int tid = threadIdx.x, warp = tid >> 5, lane = tid & 31;
    int g = lane >> 2, tg = lane & 3;
    int wm = warp >> 2, wn = warp & 3;
    int m_base = blockIdx.y * 128, n_base = blockIdx.x * 128;

    int srow[4], sc4[4];
#pragma unroll
    for (int it = 0; it < 4; it++) {
        int i = tid + it * 256;
        srow[it] = i >> 3;
        sc4[it] = i & 7;
    }

    float acc[4][4][4] = {};
    uint32_t accx[4][4][2] = {};
    float4 av[4], bv[4];

#pragma unroll
    for (int it = 0; it < 4; it++) {
        av[it] = *(const float4*)(x    + (size_t)(m_base + srow[it]) * KDIM + sc4[it] * 4);
        bv[it] = *(const float4*)(w_ih + (size_t)(n_base + srow[it]) * KDIM + sc4[it] * 4);
    }
#pragma unroll
    for (int it = 0; it < 4; it++) {
        split_pair(av[it].x, av[it].y, XA(0, 0, srow[it], sc4[it] * 2), XA(1, 0, srow[it], sc4[it] * 2));
        split_pair(av[it].z, av[it].w, XA(0, 0, srow[it], sc4[it] * 2 + 1), XA(1, 0, srow[it], sc4[it] * 2 + 1));
        split_pair(bv[it].x, bv[it].y, XA(2, 0, srow[it], sc4[it] * 2), XA(3, 0, srow[it], sc4[it] * 2));
        split_pair(bv[it].z, bv[it].w, XA(2, 0, srow[it], sc4[it] * 2 + 1), XA(3, 0, srow[it], sc4[it] * 2 + 1));
    }

#pragma unroll 1
    for (int c = 0; c < 32; c++) {
        if (c < 31) {
            int k0 = (c + 1) * 32;
#pragma unroll
            for (int it = 0; it < 4; it++) {
                av[it] = *(const float4*)(x    + (size_t)(m_base + srow[it]) * KDIM + k0 + sc4[it] * 4);
                bv[it] = *(const float4*)(w_ih + (size_t)(n_base + srow[it]) * KDIM + k0 + sc4[it] * 4);
            }
        }
        __syncthreads();
        if (c < 31) {
            int nb = (c + 1) & 1;
#pragma unroll
            for (int it = 0; it < 4; it++) {
                split_pair(av[it].x, av[it].y, XA(0, nb, srow[it], sc4[it] * 2), XA(1, nb, srow[it], sc4[it] * 2));
                split_pair(av[it].z, av[it].w, XA(0, nb, srow[it], sc4[it] * 2 + 1), XA(1, nb, srow[it], sc4[it] * 2 + 1));
                split_pair(bv[it].x, bv[it].y, XA(2, nb, srow[it], sc4[it] * 2), XA(3, nb, srow[it], sc4[it] * 2));
                split_pair(bv[it].z, bv[it].w, XA(2, nb, srow[it], sc4[it] * 2 + 1), XA(3, nb, srow[it], sc4[it] * 2 + 1));
            }
        }
        int bsel = c & 1;
#pragma unroll
        for (int kk = 0; kk < 2; kk++) {
            uint32_t afh[4][4], afm[4][4];
#pragma unroll
            for (int mi = 0; mi < 4; mi++) {
                int r = wm * 64 + mi * 16;
                afh[mi][0] = XA(0, bsel, r + g, kk * 8 + tg);
                afh[mi][1] = XA(0, bsel, r + g + 8, kk * 8 + tg);
                afh[mi][2] = XA(0, bsel, r + g, kk * 8 + tg + 4);
                afh[mi][3] = XA(0, bsel, r + g + 8, kk * 8 + tg + 4);
                afm[mi][0] = XA(1, bsel, r + g, kk * 8 + tg);
                afm[mi][1] = XA(1, bsel, r + g + 8, kk * 8 + tg);
                afm[mi][2] = XA(1, bsel, r + g, kk * 8 + tg + 4);
                afm[mi][3] = XA(1, bsel, r + g + 8, kk * 8 + tg + 4);
            }
#pragma unroll
            for (int ni = 0; ni < 4; ni++) {
                int rn = wn * 32 + ni * 8 + g;
                uint32_t bfh[2] = {XA(2, bsel, rn, kk * 8 + tg), XA(2, bsel, rn, kk * 8 + tg + 4)};
                uint32_t bfm[2] = {XA(3, bsel, rn, kk * 8 + tg), XA(3, bsel, rn, kk * 8 + tg + 4)};
#pragma unroll
                for (int mi = 0; mi < 4; mi++) {
                    mma16h(accx[mi][ni], afh[mi], bfm);
                    mma16h(accx[mi][ni], afm[mi], bfh);
                    mma16(acc[mi][ni], afh[mi], bfh);
                }
            }
        }
    }

    int bflag = *biasflag;
#pragma unroll
    for (int mi = 0; mi < 4; mi++) {
#pragma unroll
        for (int ni = 0; ni < 4; ni++) {
            merge_cross(acc[mi][ni], accx[mi][ni]);
            int row0 = m_base + wm * 64 + mi * 16 + g;
            int col0 = n_base + wn * 32 + ni * 8 + 2 * tg;
            float bs0 = bflag ? (b_ih[col0] + b_hh[col0]) : 0.0f;
            float bs1 = bflag ? (b_ih[col0 + 1] + b_hh[col0 + 1]) : 0.0f;
            g_Zx[(size_t)row0 * G4 + col0]           = acc[mi][ni][0] + bs0;
            g_Zx[(size_t)row0 * G4 + col0 + 1]       = acc[mi][ni][1] + bs1;
            g_Zx[(size_t)(row0 + 8) * G4 + col0]     = acc[mi][ni][2] + bs0;
            g_Zx[(size_t)(row0 + 8) * G4 + col0 + 1] = acc[mi][ni][3] + bs1;
        }
    }
}

// ============ Phase 2: recurrence (R10 shape, pre-split h via LDG+STS.128) =
extern __shared__ char rsm[];
#define SA4(buf, hm, row, col) sAu[((((buf) * 2 + (hm)) * 64 + (row)) * ASTR) + (col)]
__global__ void __launch_bounds__(256, 1)
recur_kernel(const float* __restrict__ c0, float* __restrict__ out) {
    uint2*    sWfH = (uint2*)rsm;
    uint2*    sWfM = sWfH + SLOTS;
    uint32_t* sAu  = (uint32_t*)(sWfM + SLOTS);          // [4 buf][2 hm][64][ASTR]
    float*    zsm  = (float*)(sAu + 4 * 2 * 64 * ASTR);

    int tid = threadIdx.x, warp = tid >> 5, lane = tid & 31;
    int g = lane >> 2, tg = lane & 3;
    int wm = warp & 3, wn = warp >> 2;
    int j0 = blockIdx.x * 8;

    {
        const uint2* gH = g_WfragH + (size_t)blockIdx.x * SLOTS;
        const uint2* gM = g_WfragM + (size_t)blockIdx.x * SLOTS;
        for (int i = tid; i < SLOTS; i += 256) {
            sWfH[i] = gH[i];
            sWfM[i] = gM[i];
        }
    }

    // Epilogue ownership: thread -> (batch b, column pair jp)
    int b = tid >> 2, jp = tid & 3;
    int col0 = j0 + 2 * jp;
    float2 cini = *(const float2*)(c0 + (size_t)b * HDIM + col0);
    float c_[2] = {cini.x, cini.y};
    float sbuf[4][2] = {};
    float hl[2] = {0.f, 0.f};

    // A-loader slots: rows r0 (tid>>3) and r0+32, uint4 col q4
    int r0 = tid >> 3, r1 = r0 + 32, q4 = tid & 7;

    size_t zbase = (size_t)b * G4 + col0;
    float2 zx[4];
#pragma unroll
    for (int q = 0; q < 4; q++)
        zx[q] = *(const float2*)(g_Zx + zbase + (size_t)q * 1024);
    __syncthreads();   // W fragments visible

    for (int t = 0; t < T_STEPS; t++) {
        size_t hb = (size_t)t * BATCH * KP;

        // Prologue: LDG chunks 0,1 (hi + mid planes, uint4)
        uint4 va[2][4];
#pragma unroll
        for (int half = 0; half < 2; half++) {
            int kp = half * 32;
            va[half][0] = *(const uint4*)(g_HsH + hb + (size_t)r0 * KP + kp + q4 * 4);
            va[half][1] = *(const uint4*)(g_HsH + hb + (size_t)r1 * KP + kp + q4 * 4);
            va[half][2] = *(const uint4*)(g_HsM + hb + (size_t)r0 * KP + kp + q4 * 4);
            va[half][3] = *(const uint4*)(g_HsM + hb + (size_t)r1 * KP + kp + q4 * 4);
        }

        float acc[2][4] = {};
        uint32_t accx[2][2] = {};
#pragma unroll 1
        for (int cc = 0; cc < 8; cc++) {
            // Store chunks 2cc, 2cc+1 (R10 order: store -> sync -> LDG -> MMA)
#pragma unroll
            for (int half = 0; half < 2; half++) {
                int bsel = (2 * cc + half) & 3;
                *(uint4*)&SA4(bsel, 0, r0, q4 * 4) = va[half][0];
                *(uint4*)&SA4(bsel, 0, r1, q4 * 4) = va[half][1];
                *(uint4*)&SA4(bsel, 1, r0, q4 * 4) = va[half][2];
                *(uint4*)&SA4(bsel, 1, r1, q4 * 4) = va[half][3];
            }
            __syncthreads();
            if (cc < 7) {
#pragma unroll
                for (int half = 0; half < 2; half++) {
                    int kp = (2 * cc + 2 + half) * 32;
                    va[half][0] = *(const uint4*)(g_HsH + hb + (size_t)r0 * KP + kp + q4 * 4);
                    va[half][1] = *(const uint4*)(g_HsH + hb + (size_t)r1 * KP + kp + q4 * 4);
                    va[half][2] = *(const uint4*)(g_HsM + hb + (size_t)r0 * KP + kp + q4 * 4);
                    va[half][3] = *(const uint4*)(g_HsM + hb + (size_t)r1 * KP + kp + q4 * 4);
                }
            }
#pragma unroll
            for (int half = 0; half < 2; half++) {
                int c = 2 * cc + half, bsel = c & 3;
#pragma unroll
                for (int kk = 0; kk < 4; kk++) {
                    uint32_t afh[4], afm[4];
                    int r = wm * 16;
                    afh[0] = SA4(bsel, 0, r + g, kk * 8 + tg);
                    afh[1] = SA4(bsel, 0, r + g + 8, kk * 8 + tg);
                    afh[2] = SA4(bsel, 0, r + g, kk * 8 + tg + 4);
                    afh[3] = SA4(bsel, 0, r + g + 8, kk * 8 + tg + 4);
                    afm[0] = SA4(bsel, 1, r + g, kk * 8 + tg);
                    afm[1] = SA4(bsel, 1, r + g + 8, kk * 8 + tg);
                    afm[2] = SA4(bsel, 1, r + g, kk * 8 + tg + 4);
                    afm[3] = SA4(bsel, 1, r + g + 8, kk * 8 + tg + 4);
#pragma unroll
                    for (int nt = 0; nt < 2; nt++) {
                        int fb = (((c * 4 + kk) * 2 + wn) * 2 + nt) * 32 + lane;
                        uint2 bh = sWfH[fb], bm = sWfM[fb];
                        uint32_t bfh[2] = {bh.x, bh.y};
                        uint32_t bfm[2] = {bm.x, bm.y};
                        mma16h(accx[nt], afh, bfm);
                        mma16h(accx[nt], afm, bfh);
                        mma16(acc[nt], afh, bfh);
                    }
                }
            }
        }
        merge_cross(acc[0], accx[0]);
        merge_cross(acc[1], accx[1]);

        // Scatter z tile
        {
            int rz = wm * 16 + g;
#pragma unroll
            for (int nt = 0; nt < 2; nt++) {
                int cw = wn * 16 + nt * 8 + 2 * tg;
                zsm[rz * 33 + cw]           = acc[nt][0];
                zsm[rz * 33 + cw + 1]       = acc[nt][1];
                zsm[(rz + 8) * 33 + cw]     = acc[nt][2];
                zsm[(rz + 8) * 33 + cw + 1] = acc[nt][3];
            }
        }
        __syncthreads();

        // Gate math + skip queue: 2 adjacent columns of batch b
        float hv[2];
#pragma unroll
        for (int e = 0; e < 2; e++) {
            int jc = 2 * jp + e;
            float zi = zsm[b * 33 + jc]      + (e ? zx[0].y : zx[0].x);
            float zf = zsm[b * 33 + 8 + jc]  + (e ? zx[1].y : zx[1].x);
            float zg = zsm[b * 33 + 16 + jc] + (e ? zx[2].y : zx[2].x);
            float zo = zsm[b * 33 + 24 + jc] + (e ? zx[3].y : zx[3].x);
            float cn = sigmf(zf) * c_[e] + sigmf(zi) * tanhf(zg);
            float h = sigmf(zo) * tanhf(cn);
            int idx = t & 3;
            if (t >= 4) h += sbuf[idx][e];
            sbuf[idx][e] = h;
            c_[e] = cn;
            hl[e] = h;
            hv[e] = h;
        }
        *(float2*)(out + (size_t)t * BATCH * HDIM + (size_t)b * HDIM + col0) =
            make_float2(hv[0], hv[1]);
        {
            uint32_t ph, pm;
            split_pair(hv[0], hv[1], ph, pm);
            size_t hi = (size_t)(t + 1) * BATCH * KP + (size_t)b * KP + blockIdx.x * 4 + jp;
            g_HsH[hi] = ph;
            g_HsM[hi] = pm;
        }

        // Prefetch next step's Zx before the barrier (step-independent data)
        if (t + 1 < T_STEPS) {
            size_t zn = (size_t)(t + 1) * BATCH * G4 + zbase;
#pragma unroll
            for (int q = 0; q < 4; q++)
                zx[q] = *(const float2*)(g_Zx + zn + (size_t)q * 1024);
        }

        // Distributed grid barrier: per-CTA release flag + 128-thread poll
        __syncthreads();
        if (tid == 0)
            asm volatile("st.release.gpu.u32 [%0], %1;"
                         :: "l"(&g_flags[blockIdx.x * 32]), "r"((unsigned)(t + 1)) : "memory");
        if (tid < NCTA) {
            unsigned v;
            do {
                asm volatile("ld.acquire.gpu.u32 %0, [%1];"
                             : "=r"(v) : "l"(&g_flags[tid * 32]) : "memory");
            } while (v < (unsigned)(t + 1));
        }
        __syncthreads();
    }

    float* hfin = out + (size_t)T_STEPS * BATCH * HDIM;
    float* cfin = hfin + BATCH * HDIM;
    *(float2*)(hfin + (size_t)b * HDIM + col0) = make_float2(hl[0], hl[1]);
    *(float2*)(cfin + (size_t)b * HDIM + col0) = make_float2(c_[0], c_[1]);
}

extern "C" void kernel_launch(void* const* d_in, const int* in_sizes, int n_in,
                              void* d_out, int out_size) {
    const float* x    = (const float*)d_in[0];
    const float* h0   = (const float*)d_in[1];
    const float* c0   = (const float*)d_in[2];
    const float* w_ih = (const float*)d_in[3];
    const float* w_hh = (const float*)d_in[4];
    const float* b_ih = (const float*)d_in[5];
    const float* b_hh = (const float*)d_in[6];
    const int* bias   = (const int*)d_in[7];
    float* out = (float*)d_out;

    const int XSMEM = 4 * 2 * 128 * XSTR * 4;                              // 81920
    const int RSMEM = SLOTS * 8 * 2 + 4 * 2 * 64 * ASTR * 4 + 64 * 33 * 4; // 213248
    cudaFuncSetAttribute(xproj_kernel, cudaFuncAttributeMaxDynamicSharedMemorySize, XSMEM);
    cudaFuncSetAttribute(recur_kernel, cudaFuncAttributeMaxDynamicSharedMemorySize, RSMEM);

    wfrag_kernel<<<(NCTA * SLOTS) / 256, 256>>>(w_hh, h0);
    dim3 g1(G4 / 128, (T_STEPS * BATCH) / 128);  // (32, 256)
    xproj_kernel<<<g1, 256, XSMEM>>>(x, w_ih, b_ih, b_hh, bias);
    recur_kernel<<<NCTA, 256, RSMEM>>>(c0, out);
}

// round 14
// speedup vs baseline: 1.5152x; 1.0553x over previous
#include <cuda_runtime.h>
#include <cuda_fp16.h>
#include <cstdint>

#define T_STEPS 512
#define BATCH   64
#define IDIM    1024
#define HDIM    1024
#define G4      4096
#define KDIM    1024
#define NCTA    128
#define SLOTS   8192            // uint2 fragment slots per CTA per array
#define ASTR    36              // recur A smem row stride (conflict-free for LDSM: 4i mod 32)
#define XSTR    20              // xproj smem row stride (16 pairs + 4 pad)

__device__ float g_Zx[(size_t)T_STEPS * BATCH * G4];
__device__ uint2 g_WfragH[(size_t)NCTA * SLOTS];
__device__ uint2 g_WfragM[(size_t)NCTA * SLOTS];
__device__ unsigned g_flags[NCTA * 32];   // distributed barrier flags, 128B apart

// ---------------------------------------------------------------- helpers
__device__ __forceinline__ void split_pair(float e, float o, uint32_t& ph, uint32_t& pm) {
    __half2 hp = __floats2half2_rn(e, o);
    float2 hf = __half22float2(hp);
    __half2 mp = __floats2half2_rn(e - hf.x, o - hf.y);
    ph = *reinterpret_cast<uint32_t*>(&hp);
    pm = *reinterpret_cast<uint32_t*>(&mp);
}
__device__ __forceinline__ void mma16(float* c, const uint32_t* a, const uint32_t* b) {
    asm volatile(
        "mma.sync.aligned.m16n8k16.row.col.f32.f16.f16.f32 "
        "{%0,%1,%2,%3},{%4,%5,%6,%7},{%8,%9},{%0,%1,%2,%3};\n"
        : "+f"(c[0]), "+f"(c[1]), "+f"(c[2]), "+f"(c[3])
        : "r"(a[0]), "r"(a[1]), "r"(a[2]), "r"(a[3]), "r"(b[0]), "r"(b[1]));
}
__device__ __forceinline__ void mma16h(uint32_t* c, const uint32_t* a, const uint32_t* b) {
    asm volatile(
        "mma.sync.aligned.m16n8k16.row.col.f16.f16.f16.f16 "
        "{%0,%1},{%2,%3,%4,%5},{%6,%7},{%0,%1};\n"
        : "+r"(c[0]), "+r"(c[1])
        : "r"(a[0]), "r"(a[1]), "r"(a[2]), "r"(a[3]), "r"(b[0]), "r"(b[1]));
}
__device__ __forceinline__ void ldsm_x4(uint32_t* r, uint32_t saddr) {
    asm volatile("ldmatrix.sync.aligned.m8n8.x4.shared.b16 {%0,%1,%2,%3}, [%4];"
                 : "=r"(r[0]), "=r"(r[1]), "=r"(r[2]), "=r"(r[3]) : "r"(saddr));
}
__device__ __forceinline__ void merge_cross(float* acc, const uint32_t* cx) {
    float2 lo = __half22float2(*reinterpret_cast<const __half2*>(&cx[0]));
    float2 hi = __half22float2(*reinterpret_cast<const __half2*>(&cx[1]));
    acc[0] += lo.x; acc[1] += lo.y; acc[2] += hi.x; acc[3] += hi.y;
}
__device__ __forceinline__ float sigmf(float x) { return 1.0f / (1.0f + expf(-x)); }

// ====== wfrag: permute w_hh into per-CTA MMA-fragment order; reset flags ===
__global__ void __launch_bounds__(256)
wfrag_kernel(const float* __restrict__ w_hh) {
    size_t s = (size_t)blockIdx.x * 256 + threadIdx.x;
    if (s < NCTA) g_flags[s * 32] = 0u;
    int cta = (int)(s >> 13);
    int r = (int)(s & (SLOTS - 1));
    int lane = r & 31, q = r >> 5;
    int nt = q & 1, wn = (q >> 1) & 1, kk = (q >> 2) & 3, c = q >> 4;
    int g = lane >> 2, tg = lane & 3;
    int row = wn * 16 + nt * 8 + g;
    size_t R = (size_t)((row >> 3) * HDIM + cta * 8 + (row & 7));
    int p0 = c * 32 + kk * 8 + tg;
    const float* wr = w_hh + R * KDIM;
    uint32_t h0w, m0w, h1w, m1w;
    split_pair(wr[2 * p0],     wr[2 * p0 + 1], h0w, m0w);
    split_pair(wr[2 * p0 + 8], wr[2 * p0 + 9], h1w, m1w);
    g_WfragH[s] = make_uint2(h0w, h1w);
    g_WfragM[s] = make_uint2(m0w, m1w);
}

// ============ Phase 1: Z_x = x @ w_ih^T + bias (R10-exact) =================
extern __shared__ uint32_t xsm_u[];
#define XA(arr, buf, row, col) xsm_u[((((arr) * 2 + (buf)) * 128 + (row)) * XSTR) + (col)]
__global__ void __launch_bounds__(256)
xproj_kernel(const float* __restrict__ x, const float* __restrict__ w_ih,
             const float* __restrict__ b_ih, const float* __restrict__ b_hh,
             const int* __restrict__ biasflag) {
    int tid = threadIdx.x, warp = tid >> 5, lane = tid & 31;
    int g = lane >> 2, tg = lane & 3;
    int wm = warp >> 2, wn = warp & 3;
    int m_base = blockIdx.y * 128, n_base = blockIdx.x * 128;

    int srow[4], sc4[4];
#pragma unroll
    for (int it = 0; it < 4; it++) {
        int i = tid + it * 256;
        srow[it] = i >> 3;
        sc4[it] = i & 7;
    }

    float acc[4][4][4] = {};
    uint32_t accx[4][4][2] = {};
    float4 av[4], bv[4];

#pragma unroll
    for (int it = 0; it < 4; it++) {
        av[it] = *(const float4*)(x    + (size_t)(m_base + srow[it]) * KDIM + sc4[it] * 4);
        bv[it] = *(const float4*)(w_ih + (size_t)(n_base + srow[it]) * KDIM + sc4[it] * 4);
    }
#pragma unroll
    for (int it = 0; it < 4; it++) {
        split_pair(av[it].x, av[it].y, XA(0, 0, srow[it], sc4[it] * 2), XA(1, 0, srow[it], sc4[it] * 2));
        split_pair(av[it].z, av[it].w, XA(0, 0, srow[it], sc4[it] * 2 + 1), XA(1, 0, srow[it], sc4[it] * 2 + 1));
        split_pair(bv[it].x, bv[it].y, XA(2, 0, srow[it], sc4[it] * 2), XA(3, 0, srow[it], sc4[it] * 2));
        split_pair(bv[it].z, bv[it].w, XA(2, 0, srow[it], sc4[it] * 2 + 1), XA(3, 0, srow[it], sc4[it] * 2 + 1));
    }

#pragma unroll 1
    for (int c = 0; c < 32; c++) {
        if (c < 31) {
            int k0 = (c + 1) * 32;
#pragma unroll
            for (int it = 0; it < 4; it++) {
                av[it] = *(const float4*)(x    + (size_t)(m_base + srow[it]) * KDIM + k0 + sc4[it] * 4);
                bv[it] = *(const float4*)(w_ih + (size_t)(n_base + srow[it]) * KDIM + k0 + sc4[it] * 4);
            }
        }
        __syncthreads();
        if (c < 31) {
            int nb = (c + 1) & 1;
#pragma unroll
            for (int it = 0; it < 4; it++) {
                split_pair(av[it].x, av[it].y, XA(0, nb, srow[it], sc4[it] * 2), XA(1, nb, srow[it], sc4[it] * 2));
                split_pair(av[it].z, av[it].w, XA(0, nb, srow[it], sc4[it] * 2 + 1), XA(1, nb, srow[it], sc4[it] * 2 + 1));
                split_pair(bv[it].x, bv[it].y, XA(2, nb, srow[it], sc4[it] * 2), XA(3, nb, srow[it], sc4[it] * 2));
                split_pair(bv[it].z, bv[it].w, XA(2, nb, srow[it], sc4[it] * 2 + 1), XA(3, nb, srow[it], sc4[it] * 2 + 1));
            }
        }
        int bsel = c & 1;
#pragma unroll
        for (int kk = 0; kk < 2; kk++) {
            uint32_t afh[4][4], afm[4][4];
#pragma unroll
            for (int mi = 0; mi < 4; mi++) {
                int r = wm * 64 + mi * 16;
                afh[mi][0] = XA(0, bsel, r + g, kk * 8 + tg);
                afh[mi][1] = XA(0, bsel, r + g + 8, kk * 8 + tg);
                afh[mi][2] = XA(0, bsel, r + g, kk * 8 + tg + 4);
                afh[mi][3] = XA(0, bsel, r + g + 8, kk * 8 + tg + 4);
                afm[mi][0] = XA(1, bsel, r + g, kk * 8 + tg);
                afm[mi][1] = XA(1, bsel, r + g + 8, kk * 8 + tg);
                afm[mi][2] = XA(1, bsel, r + g, kk * 8 + tg + 4);
                afm[mi][3] = XA(1, bsel, r + g + 8, kk * 8 + tg + 4);
            }
#pragma unroll
            for (int ni = 0; ni < 4; ni++) {
                int rn = wn * 32 + ni * 8 + g;
                uint32_t bfh[2] = {XA(2, bsel, rn, kk * 8 + tg), XA(2, bsel, rn, kk * 8 + tg + 4)};
                uint32_t bfm[2] = {XA(3, bsel, rn, kk * 8 + tg), XA(3, bsel, rn, kk * 8 + tg + 4)};
#pragma unroll
                for (int mi = 0; mi < 4; mi++) {
                    mma16h(accx[mi][ni], afh[mi], bfm);
                    mma16h(accx[mi][ni], afm[mi], bfh);
                    mma16(acc[mi][ni], afh[mi], bfh);
                }
            }
        }
    }

    int bflag = *biasflag;
#pragma unroll
    for (int mi = 0; mi < 4; mi++) {
#pragma unroll
        for (int ni = 0; ni < 4; ni++) {
            merge_cross(acc[mi][ni], accx[mi][ni]);
            int row0 = m_base + wm * 64 + mi * 16 + g;
            int col0 = n_base + wn * 32 + ni * 8 + 2 * tg;
            float bs0 = bflag ? (b_ih[col0] + b_hh[col0]) : 0.0f;
            float bs1 = bflag ? (b_ih[col0 + 1] + b_hh[col0 + 1]) : 0.0f;
            g_Zx[(size_t)row0 * G4 + col0]           = acc[mi][ni][0] + bs0;
            g_Zx[(size_t)row0 * G4 + col0 + 1]       = acc[mi][ni][1] + bs1;
            g_Zx[(size_t)(row0 + 8) * G4 + col0]     = acc[mi][ni][2] + bs0;
            g_Zx[(size_t)(row0 + 8) * G4 + col0 + 1] = acc[mi][ni][3] + bs1;
        }
    }
}

// ============ Phase 2: recurrence (R10 + ldmatrix A-fragment loads) ========
extern __shared__ char rsm[];
#define SA4(buf, hm, row, col) sAu[((((buf) * 2 + (hm)) * 64 + (row)) * ASTR) + (col)]
__global__ void __launch_bounds__(256, 1)
recur_kernel(const float* __restrict__ h0, const float* __restrict__ c0,
             float* __restrict__ out) {
    uint2*    sWfH = (uint2*)rsm;
    uint2*    sWfM = sWfH + SLOTS;
    uint32_t* sAu  = (uint32_t*)(sWfM + SLOTS);          // [4 buf][2 hm][64][ASTR]
    float*    zsm  = (float*)(sAu + 4 * 2 * 64 * ASTR);

    int tid = threadIdx.x, warp = tid >> 5, lane = tid & 31;
    int g = lane >> 2, tg = lane & 3;
    int wm = warp & 3, wn = warp >> 2;
    int j0 = blockIdx.x * 8;

    {
        const uint2* gH = g_WfragH + (size_t)blockIdx.x * SLOTS;
        const uint2* gM = g_WfragM + (size_t)blockIdx.x * SLOTS;
        for (int i = tid; i < SLOTS; i += 256) {
            sWfH[i] = gH[i];
            sWfM[i] = gM[i];
        }
    }

    int b0e = tid >> 3, jj0 = tid & 7;
    int b1e = (tid + 256) >> 3, jj1 = (tid + 256) & 7;
    float creg0 = c0[b0e * HDIM + j0 + jj0];
    float creg1 = c0[b1e * HDIM + j0 + jj1];
    float buf0[4] = {0.f, 0.f, 0.f, 0.f};
    float buf1[4] = {0.f, 0.f, 0.f, 0.f};
    float hlast0 = 0.f, hlast1 = 0.f;

    int arow[4], ac4[4];
#pragma unroll
    for (int it = 0; it < 4; it++) {
        int i = tid + it * 256;
        arow[it] = i >> 4;
        ac4[it] = i & 15;
    }

    // ldmatrix lane addressing: row = wm*16 + (lane&7) + ((lane>>3)&1)*8,
    //                           pair = kk*8 + (lane>>4)*4
    uint32_t sA_base = (uint32_t)__cvta_generic_to_shared(sAu);
    int lrow = wm * 16 + (lane & 7) + ((lane >> 3) & 1) * 8;
    uint32_t lrow_off = (uint32_t)(lrow * ASTR) * 4;
    uint32_t lcol_off = (uint32_t)((lane >> 4) * 4) * 4;
    const uint32_t HM_OFF  = (uint32_t)(64 * ASTR) * 4;       // hm=0 -> hm=1
    const uint32_t BUF_OFF = (uint32_t)(2 * 64 * ASTR) * 4;   // buf stride

    size_t zb0 = (size_t)b0e * G4 + (j0 + jj0);
    size_t zb1 = (size_t)b1e * G4 + (j0 + jj1);
    float zx0[4], zx1[4];
#pragma unroll
    for (int q = 0; q < 4; q++) {
        zx0[q] = g_Zx[zb0 + (size_t)q * 1024];
        zx1[q] = g_Zx[zb1 + (size_t)q * 1024];
    }
    __syncthreads();   // W fragments visible

    for (int t = 0; t < T_STEPS; t++) {
        const float* hsrc = (t == 0) ? h0 : (out + (size_t)(t - 1) * BATCH * HDIM);

        // Prologue: LDG chunks 0,1
        float4 va[2][4];
#pragma unroll
        for (int half = 0; half < 2; half++)
#pragma unroll
            for (int it = 0; it < 4; it++)
                va[half][it] = *(const float4*)(hsrc + (size_t)arow[it] * HDIM +
                                                half * 64 + ac4[it] * 4);

        float acc[2][4] = {};
        uint32_t accx[2][2] = {};
#pragma unroll 1
        for (int cc = 0; cc < 8; cc++) {
            // split chunks 2cc, 2cc+1 (R10 order: split -> sync -> LDG -> MMA)
#pragma unroll
            for (int half = 0; half < 2; half++) {
                int bsel = (2 * cc + half) & 3;
#pragma unroll
                for (int it = 0; it < 4; it++) {
                    split_pair(va[half][it].x, va[half][it].y,
                               SA4(bsel, 0, arow[it], ac4[it] * 2),
                               SA4(bsel, 1, arow[it], ac4[it] * 2));
                    split_pair(va[half][it].z, va[half][it].w,
                               SA4(bsel, 0, arow[it], ac4[it] * 2 + 1),
                               SA4(bsel, 1, arow[it], ac4[it] * 2 + 1));
                }
            }
            __syncthreads();
            if (cc < 7) {
#pragma unroll
                for (int half = 0; half < 2; half++) {
                    int k0 = (2 * cc + 2 + half) * 64;
#pragma unroll
                    for (int it = 0; it < 4; it++)
                        va[half][it] = *(const float4*)(hsrc + (size_t)arow[it] * HDIM +
                                                        k0 + ac4[it] * 4);
                }
            }
#pragma unroll
            for (int half = 0; half < 2; half++) {
                int c = 2 * cc + half, bsel = c & 3;
                uint32_t abase = sA_base + (uint32_t)bsel * BUF_OFF + lrow_off + lcol_off;
#pragma unroll
                for (int kk = 0; kk < 4; kk++) {
                    uint32_t afh[4], afm[4];
                    uint32_t ka = abase + (uint32_t)(kk * 8) * 4;
                    ldsm_x4(afh, ka);
                    ldsm_x4(afm, ka + HM_OFF);
#pragma unroll
                    for (int nt = 0; nt < 2; nt++) {
                        int fb = (((c * 4 + kk) * 2 + wn) * 2 + nt) * 32 + lane;
                        uint2 bh = sWfH[fb], bm = sWfM[fb];
                        uint32_t bfh[2] = {bh.x, bh.y};
                        uint32_t bfm[2] = {bm.x, bm.y};
                        mma16h(accx[nt], afh, bfm);
                        mma16h(accx[nt], afm, bfh);
                        mma16(acc[nt], afh, bfh);
                    }
                }
            }
        }
        merge_cross(acc[0], accx[0]);
        merge_cross(acc[1], accx[1]);

        // Scatter z tile (zsm disjoint from sA)
        {
            int r0 = wm * 16 + g;
#pragma unroll
            for (int nt = 0; nt < 2; nt++) {
                int cc2 = wn * 16 + nt * 8 + 2 * tg;
                zsm[r0 * 33 + cc2]           = acc[nt][0];
                zsm[r0 * 33 + cc2 + 1]       = acc[nt][1];
                zsm[(r0 + 8) * 33 + cc2]     = acc[nt][2];
                zsm[(r0 + 8) * 33 + cc2 + 1] = acc[nt][3];
            }
        }
        __syncthreads();

        {
            float zi = zsm[b0e * 33 + jj0]      + zx0[0];
            float zf = zsm[b0e * 33 + 8 + jj0]  + zx0[1];
            float zg = zsm[b0e * 33 + 16 + jj0] + zx0[2];
            float zo = zsm[b0e * 33 + 24 + jj0] + zx0[3];
            float cn = sigmf(zf) * creg0 + sigmf(zi) * tanhf(zg);
            float h = sigmf(zo) * tanhf(cn);
            int idx = t & 3;
            if (t >= 4) h += buf0[idx];
            buf0[idx] = h;
            creg0 = cn;
            hlast0 = h;
            out[(size_t)t * BATCH * HDIM + b0e * HDIM + j0 + jj0] = h;
        }
        {
            float zi = zsm[b1e * 33 + jj1]      + zx1[0];
            float zf = zsm[b1e * 33 + 8 + jj1]  + zx1[1];
            float zg = zsm[b1e * 33 + 16 + jj1] + zx1[2];
            float zo = zsm[b1e * 33 + 24 + jj1] + zx1[3];
            float cn = sigmf(zf) * creg1 + sigmf(zi) * tanhf(zg);
            float h = sigmf(zo) * tanhf(cn);
            int idx = t & 3;
            if (t >= 4) h += buf1[idx];
            buf1[idx] = h;
            creg1 = cn;
            hlast1 = h;
            out[(size_t)t * BATCH * HDIM + b1e * HDIM + j0 + jj1] = h;
        }

        if (t + 1 < T_STEPS) {
            size_t zn = (size_t)(t + 1) * BATCH * G4;
#pragma unroll
            for (int q = 0; q < 4; q++) {
                zx0[q] = g_Zx[zn + zb0 + (size_t)q * 1024];
                zx1[q] = g_Zx[zn + zb1 + (size_t)q * 1024];
            }
        }

        // Distributed grid barrier: per-CTA release flag + 128-thread poll
        __syncthreads();
        if (tid == 0)
            asm volatile("st.release.gpu.u32 [%0], %1;"
                         :: "l"(&g_flags[blockIdx.x * 32]), "r"((unsigned)(t + 1)) : "memory");
        if (tid < NCTA) {
            unsigned v;
            do {
                asm volatile("ld.acquire.gpu.u32 %0, [%1];"
                             : "=r"(v) : "l"(&g_flags[tid * 32]) : "memory");
            } while (v < (unsigned)(t + 1));
        }
        __syncthreads();
    }

    float* hfin = out + (size_t)T_STEPS * BATCH * HDIM;
    float* cfin = hfin + BATCH * HDIM;
    hfin[b0e * HDIM + j0 + jj0] = hlast0;
    hfin[b1e * HDIM + j0 + jj1] = hlast1;
    cfin[b0e * HDIM + j0 + jj0] = creg0;
    cfin[b1e * HDIM + j0 + jj1] = creg1;
}

extern "C" void kernel_launch(void* const* d_in, const int* in_sizes, int n_in,
                              void* d_out, int out_size) {
    const float* x    = (const float*)d_in[0];
    const float* h0   = (const float*)d_in[1];
    const float* c0   = (const float*)d_in[2];
    const float* w_ih = (const float*)d_in[3];
    const float* w_hh = (const float*)d_in[4];
    const float* b_ih = (const float*)d_in[5];
    const float* b_hh = (const float*)d_in[6];
    const int* bias   = (const int*)d_in[7];
    float* out = (float*)d_out;

    const int XSMEM = 4 * 2 * 128 * XSTR * 4;                              // 81920
    const int RSMEM = SLOTS * 8 * 2 + 4 * 2 * 64 * ASTR * 4 + 64 * 33 * 4; // 213248
    cudaFuncSetAttribute(xproj_kernel, cudaFuncAttributeMaxDynamicSharedMemorySize, XSMEM);
    cudaFuncSetAttribute(recur_kernel, cudaFuncAttributeMaxDynamicSharedMemorySize, RSMEM);

    wfrag_kernel<<<(NCTA * SLOTS) / 256, 256>>>(w_hh);
    dim3 g1(G4 / 128, (T_STEPS * BATCH) / 128);  // (32, 256)
    xproj_kernel<<<g1, 256, XSMEM>>>(x, w_ih, b_ih, b_hh, bias);
    recur_kernel<<<NCTA, 256, RSMEM>>>(h0, c0, out);
}